// round 1
// baseline (speedup 1.0000x reference)
#include <cuda_runtime.h>
#include <math.h>

#define BB 16
#define SSQ 256
#define TTQ 128
#define DDQ 512
#define VVQ 32000
#define LLQ 3
#define R2F 0.70710678118654752440f

// ---------------- scratch (single __device__ array, no allocs) ----------------
// offsets (floats):
//  enc_emb     0          2,097,152   [B,S,D]
//  enc_x       2,097,152  2,097,152   [B,D,S]
//  im2col      4,194,304  6,291,456   [B,3D,S] (dec reuses)
//  ybuf       10,485,760  4,194,304   [B,2D,S] (dec reuses)
//  enc_conved 14,680,064  2,097,152   [B,S,D]
//  enc_comb   16,777,216  2,097,152   [B,S,D]
//  dec_emb    18,874,368  1,048,576   [B,T,D]
//  dec_x      19,922,944  1,048,576   [B,D,T]
//  dec_c      20,971,520  1,048,576   [B,D,T]
//  qbuf       22,020,096  1,048,576   [B,T,D] (also final dec_conved)
//  energy     23,068,672    524,288   [B,T,S]
//  att        23,592,960  1,048,576   [B,T,D]
//  att2       24,641,536  1,048,576   [B*T,D]
__device__ float g_scratch[25690112];

// ---------------- generic batched SGEMM ----------------
// C[bz][m][n] = epilogue( sum_k A[bz*a_b + m*a_sm + k*a_sk] * B[bz*b_b + k*b_sk + n*b_sn] + bias )
struct GemmP {
    const float* A; long long a_sm, a_sk, a_b;
    const float* Bm; long long b_sk, b_sn, b_b;
    float* C; long long c_row, c_b;
    const float* bias; int bias_per_m;
    int M, N, K, mode;           // mode: 0 plain, 1 enc-out (pad zero + combined), 2 (+emb)*R2
    const int* tokens;           // mode 1: src tokens [B,S]
    const float* emb; long long emb_b;
    float* C2;                   // mode 1: combined output
};

__global__ __launch_bounds__(256) void sgemm_kernel(GemmP p) {
    __shared__ float As[8][128];
    __shared__ float Bs[8][128];
    int bz = blockIdx.z;
    long long Abase = (long long)bz * p.a_b;
    long long Bbase = (long long)bz * p.b_b;
    int m0 = blockIdx.y * 128, n0 = blockIdx.x * 128;
    int tid = threadIdx.x;
    int tx = tid & 15, ty = tid >> 4;

    float acc[8][8];
#pragma unroll
    for (int i = 0; i < 8; i++)
#pragma unroll
        for (int j = 0; j < 8; j++) acc[i][j] = 0.f;

    for (int k0 = 0; k0 < p.K; k0 += 8) {
#pragma unroll
        for (int q = 0; q < 4; q++) {
            int j = tid + q * 256;
            int mm = j & 127, kk = j >> 7;
            As[kk][mm] = p.A[Abase + (long long)(m0 + mm) * p.a_sm + (long long)(k0 + kk) * p.a_sk];
            Bs[kk][mm] = p.Bm[Bbase + (long long)(k0 + kk) * p.b_sk + (long long)(n0 + mm) * p.b_sn];
        }
        __syncthreads();
#pragma unroll
        for (int kk = 0; kk < 8; kk++) {
            float4 a0 = *(const float4*)&As[kk][ty * 4];
            float4 a1 = *(const float4*)&As[kk][64 + ty * 4];
            float4 b0 = *(const float4*)&Bs[kk][tx * 4];
            float4 b1 = *(const float4*)&Bs[kk][64 + tx * 4];
            float av[8] = {a0.x, a0.y, a0.z, a0.w, a1.x, a1.y, a1.z, a1.w};
            float bv[8] = {b0.x, b0.y, b0.z, b0.w, b1.x, b1.y, b1.z, b1.w};
#pragma unroll
            for (int i = 0; i < 8; i++)
#pragma unroll
                for (int j = 0; j < 8; j++) acc[i][j] += av[i] * bv[j];
        }
        __syncthreads();
    }

#pragma unroll
    for (int i = 0; i < 8; i++) {
        int m = m0 + ((i < 4) ? (ty * 4 + i) : (64 + ty * 4 + i - 4));
#pragma unroll
        for (int j = 0; j < 8; j++) {
            int n = n0 + ((j < 4) ? (tx * 4 + j) : (64 + tx * 4 + j - 4));
            float v = acc[i][j];
            if (p.bias) v += p.bias_per_m ? p.bias[m] : p.bias[n];
            long long cidx = (long long)bz * p.c_b + (long long)m * p.c_row + n;
            if (p.mode == 0) {
                p.C[cidx] = v;
            } else if (p.mode == 1) {
                int tok = p.tokens[bz * SSQ + m];
                float conved = (tok == 0) ? 0.f : v;
                p.C[cidx] = conved;
                float e = p.emb[(long long)bz * p.emb_b + (long long)m * p.N + n];
                p.C2[cidx] = (conved + e) * R2F;
            } else { // mode 2
                float e = p.emb[(long long)bz * p.emb_b + (long long)m * p.N + n];
                p.C[cidx] = (v + e) * R2F;
            }
        }
    }
}

// ---------------- embeddings ----------------
__global__ void embed_kernel(const int* __restrict__ tokens, const float* __restrict__ tok_emb,
                             const float* __restrict__ pos_emb, float* __restrict__ out, int Slen) {
    int b = blockIdx.y;
    __shared__ int pos[SSQ];
    if (threadIdx.x == 0) {
        int c = 0;
        for (int s = 0; s < Slen; s++) {
            int m = (tokens[b * Slen + s] != 0) ? 1 : 0;
            c += m;
            pos[s] = c * m;
        }
    }
    __syncthreads();
    int chunk = Slen / gridDim.x;
    int s0 = blockIdx.x * chunk;
    for (int idx = threadIdx.x; idx < chunk * DDQ; idx += blockDim.x) {
        int s = s0 + idx / DDQ;
        int d = idx % DDQ;
        int tk = tokens[b * Slen + s];
        out[((long long)b * Slen + s) * DDQ + d] =
            tok_emb[(long long)tk * DDQ + d] + pos_emb[(long long)pos[s] * DDQ + d];
    }
}

// ---------------- im2col (row order ic*3+k so weights are contiguous) ----------------
__global__ void im2col_enc_kernel(const float* __restrict__ x, const int* __restrict__ tokens,
                                  float* __restrict__ out, int total) {
    int idx = blockIdx.x * blockDim.x + threadIdx.x;
    if (idx >= total) return;
    int s = idx % SSQ;
    int r = (idx / SSQ) % (3 * DDQ);
    int b = idx / (SSQ * 3 * DDQ);
    int ic = r / 3, k = r % 3;
    int s2 = s + k - 1;
    float v = 0.f;
    if (s2 >= 0 && s2 < SSQ && tokens[b * SSQ + s2] != 0)
        v = x[((long long)b * DDQ + ic) * SSQ + s2];
    out[idx] = v;
}

__global__ void im2col_dec_kernel(const float* __restrict__ x, float* __restrict__ out, int total) {
    int idx = blockIdx.x * blockDim.x + threadIdx.x;
    if (idx >= total) return;
    int t = idx % TTQ;
    int r = (idx / TTQ) % (3 * DDQ);
    int b = idx / (TTQ * 3 * DDQ);
    int ic = r / 3, k = r % 3;
    int t2 = t + k - 2;  // causal: pad K-1=2 left
    out[idx] = (t2 >= 0) ? x[((long long)b * DDQ + ic) * TTQ + t2] : 0.f;
}

// ---------------- GLU (+ optional residual, in place on x) ----------------
__global__ void glu_res_kernel(const float* __restrict__ y, float* __restrict__ x,
                               int total, int DS, int apply_res) {
    int idx = blockIdx.x * blockDim.x + threadIdx.x;
    if (idx >= total) return;
    int b = idx / DS;
    int rem = idx - b * DS;
    float a = y[(long long)b * 2 * DS + rem];
    float g = y[(long long)b * 2 * DS + DS + rem];
    float v = a / (1.f + expf(-g));
    x[idx] = apply_res ? (v + x[idx]) * R2F : v;
}

// ---------------- decoder combine: x = ((c + att2^T)*R2 + x)*R2 ----------------
__global__ void dec_combine_kernel(float* __restrict__ x, const float* __restrict__ c,
                                   const float* __restrict__ att2, int total) {
    int idx = blockIdx.x * blockDim.x + threadIdx.x;
    if (idx >= total) return;
    int b = idx / (DDQ * TTQ);
    int rem = idx - b * (DDQ * TTQ);
    int ch = rem / TTQ;
    int t = rem % TTQ;
    float cc = (c[idx] + att2[((long long)b * TTQ + t) * DDQ + ch]) * R2F;
    x[idx] = (cc + x[idx]) * R2F;
}

// ---------------- masked softmax over S ----------------
__global__ void softmax_mask_kernel(float* __restrict__ energy, const int* __restrict__ src) {
    int row = blockIdx.x;           // b*T + t
    int b = row / TTQ;
    float* e = energy + (long long)row * SSQ;
    int s = threadIdx.x;            // 256 = S
    float v = (src[b * SSQ + s] == 0) ? -INFINITY : e[s];
    __shared__ float red[SSQ];
    red[s] = v;
    __syncthreads();
    for (int off = 128; off > 0; off >>= 1) {
        if (s < off) red[s] = fmaxf(red[s], red[s + off]);
        __syncthreads();
    }
    float mx = red[0];
    __syncthreads();
    float ex = expf(v - mx);
    red[s] = ex;
    __syncthreads();
    for (int off = 128; off > 0; off >>= 1) {
        if (s < off) red[s] += red[s + off];
        __syncthreads();
    }
    e[s] = ex / red[0];
}

// ---------------- host side ----------------
static void gemm(const float* A, long long a_sm, long long a_sk, long long a_b,
                 const float* Bm, long long b_sk, long long b_sn, long long b_b,
                 float* C, long long c_row, long long c_b,
                 const float* bias, int bias_per_m,
                 int M, int N, int K, int nb,
                 int mode = 0, const int* tokens = nullptr,
                 const float* emb = nullptr, long long emb_b = 0, float* C2 = nullptr) {
    GemmP p;
    p.A = A; p.a_sm = a_sm; p.a_sk = a_sk; p.a_b = a_b;
    p.Bm = Bm; p.b_sk = b_sk; p.b_sn = b_sn; p.b_b = b_b;
    p.C = C; p.c_row = c_row; p.c_b = c_b;
    p.bias = bias; p.bias_per_m = bias_per_m;
    p.M = M; p.N = N; p.K = K; p.mode = mode;
    p.tokens = tokens; p.emb = emb; p.emb_b = emb_b; p.C2 = C2;
    dim3 grid(N / 128, M / 128, nb);
    sgemm_kernel<<<grid, 256>>>(p);
}

extern "C" void kernel_launch(void* const* d_in, const int* in_sizes, int n_in,
                              void* d_out, int out_size) {
    const int*   src        = (const int*)d_in[0];
    const int*   trg        = (const int*)d_in[1];
    const float* enc_tok    = (const float*)d_in[2];
    const float* enc_pos    = (const float*)d_in[3];
    const float* dec_tok    = (const float*)d_in[4];
    const float* dec_pos    = (const float*)d_in[5];
    const float* enc_in_w   = (const float*)d_in[6];
    const float* enc_in_b   = (const float*)d_in[7];
    const float* enc_conv_w = (const float*)d_in[8];
    const float* enc_conv_b = (const float*)d_in[9];
    const float* enc_out_w  = (const float*)d_in[10];
    const float* enc_out_b  = (const float*)d_in[11];
    const float* dec_in_w   = (const float*)d_in[12];
    const float* dec_in_b   = (const float*)d_in[13];
    const float* dec_conv_w = (const float*)d_in[14];
    const float* dec_conv_b = (const float*)d_in[15];
    const float* attn_in_w  = (const float*)d_in[16];
    const float* attn_in_b  = (const float*)d_in[17];
    const float* attn_out_w = (const float*)d_in[18];
    const float* attn_out_b = (const float*)d_in[19];
    const float* dec_out_w  = (const float*)d_in[20];
    const float* dec_out_b  = (const float*)d_in[21];
    const float* vocab_w    = (const float*)d_in[22];
    const float* vocab_b    = (const float*)d_in[23];
    float* logits = (float*)d_out;

    void* sp;
    cudaGetSymbolAddress(&sp, g_scratch);
    float* base = (float*)sp;
    float* enc_emb    = base;
    float* enc_x      = base + 2097152;
    float* im2col     = base + 4194304;
    float* ybuf       = base + 10485760;
    float* enc_conved = base + 14680064;
    float* enc_comb   = base + 16777216;
    float* dec_emb    = base + 18874368;
    float* dec_x      = base + 19922944;
    float* dec_c      = base + 20971520;
    float* qbuf       = base + 22020096;
    float* energy     = base + 23068672;
    float* att        = base + 23592960;
    float* att2       = base + 24641536;

    // ---- embeddings ----
    embed_kernel<<<dim3(4, BB), 256>>>(src, enc_tok, enc_pos, enc_emb, SSQ);
    embed_kernel<<<dim3(4, BB), 256>>>(trg, dec_tok, dec_pos, dec_emb, TTQ);

    // ---- encoder in-projection -> x[b][c][s] ----
    gemm(enc_in_w, 1, DDQ, 0,
         enc_emb, 1, DDQ, (long long)SSQ * DDQ,
         enc_x, SSQ, (long long)DDQ * SSQ,
         enc_in_b, 1, DDQ, SSQ, DDQ, BB);

    // ---- encoder conv stack ----
    for (int l = 0; l < LLQ; l++) {
        int tot = BB * DDQ * 3 * SSQ;
        im2col_enc_kernel<<<(tot + 255) / 256, 256>>>(enc_x, src, im2col, tot);
        gemm(enc_conv_w + (long long)l * 2 * DDQ * DDQ * 3, 3 * DDQ, 1, 0,
             im2col, SSQ, 1, (long long)3 * DDQ * SSQ,
             ybuf, SSQ, (long long)2 * DDQ * SSQ,
             enc_conv_b + l * 2 * DDQ, 1, 2 * DDQ, SSQ, 3 * DDQ, BB);
        int tot2 = BB * DDQ * SSQ;
        glu_res_kernel<<<(tot2 + 255) / 256, 256>>>(ybuf, enc_x, tot2, DDQ * SSQ, 1);
    }

    // ---- encoder out-projection (+pad mask, combined) ----
    gemm(enc_x, 1, SSQ, (long long)DDQ * SSQ,
         enc_out_w, DDQ, 1, 0,
         enc_conved, DDQ, (long long)SSQ * DDQ,
         enc_out_b, 0, SSQ, DDQ, DDQ, BB,
         1, src, enc_emb, (long long)SSQ * DDQ, enc_comb);

    // ---- decoder in-projection -> x[b][c][t] ----
    gemm(dec_in_w, 1, DDQ, 0,
         dec_emb, 1, DDQ, (long long)TTQ * DDQ,
         dec_x, TTQ, (long long)DDQ * TTQ,
         dec_in_b, 1, DDQ, TTQ, DDQ, BB);

    // ---- decoder layers ----
    for (int l = 0; l < LLQ; l++) {
        int tot = BB * DDQ * 3 * TTQ;
        im2col_dec_kernel<<<(tot + 255) / 256, 256>>>(dec_x, im2col, tot);
        gemm(dec_conv_w + (long long)l * 2 * DDQ * DDQ * 3, 3 * DDQ, 1, 0,
             im2col, TTQ, 1, (long long)3 * DDQ * TTQ,
             ybuf, TTQ, (long long)2 * DDQ * TTQ,
             dec_conv_b + l * 2 * DDQ, 1, 2 * DDQ, TTQ, 3 * DDQ, BB);
        int tot2 = BB * DDQ * TTQ;
        glu_res_kernel<<<(tot2 + 255) / 256, 256>>>(ybuf, dec_c, tot2, DDQ * TTQ, 0);

        // q = (c^T @ Wq + bq + emb) * R2
        gemm(dec_c, 1, TTQ, (long long)DDQ * TTQ,
             attn_in_w + (long long)l * DDQ * DDQ, DDQ, 1, 0,
             qbuf, DDQ, (long long)TTQ * DDQ,
             attn_in_b + l * DDQ, 0, TTQ, DDQ, DDQ, BB,
             2, nullptr, dec_emb, (long long)TTQ * DDQ, nullptr);

        // energy = q @ enc_conved^T
        gemm(qbuf, DDQ, 1, (long long)TTQ * DDQ,
             enc_conved, 1, DDQ, (long long)SSQ * DDQ,
             energy, SSQ, (long long)TTQ * SSQ,
             nullptr, 0, TTQ, SSQ, DDQ, BB);

        softmax_mask_kernel<<<BB * TTQ, SSQ>>>(energy, src);

        // att = attn @ enc_combined
        gemm(energy, SSQ, 1, (long long)TTQ * SSQ,
             enc_comb, DDQ, 1, (long long)SSQ * DDQ,
             att, DDQ, (long long)TTQ * DDQ,
             nullptr, 0, TTQ, DDQ, SSQ, BB);

        // att2 = att @ Wout + bout
        gemm(att, DDQ, 1, 0,
             attn_out_w + (long long)l * DDQ * DDQ, DDQ, 1, 0,
             att2, DDQ, 0,
             attn_out_b + l * DDQ, 0, BB * TTQ, DDQ, DDQ, 1);

        int tot3 = BB * DDQ * TTQ;
        dec_combine_kernel<<<(tot3 + 255) / 256, 256>>>(dec_x, dec_c, att2, tot3);
    }

    // ---- decoder out-projection -> [B,T,D] (reuse qbuf) ----
    gemm(dec_x, 1, TTQ, (long long)DDQ * TTQ,
         dec_out_w, DDQ, 1, 0,
         qbuf, DDQ, (long long)TTQ * DDQ,
         dec_out_b, 0, TTQ, DDQ, DDQ, BB);

    // ---- vocab projection -> logits [B*T, V] ----
    gemm(qbuf, DDQ, 1, 0,
         vocab_w, VVQ, 1, 0,
         logits, VVQ, 0,
         vocab_b, 0, BB * TTQ, VVQ, DDQ, 1);
}

// round 3
// speedup vs baseline: 1.5771x; 1.5771x over previous
#include <cuda_runtime.h>
#include <math.h>

#define BB 16
#define SSQ 256
#define TTQ 128
#define DDQ 512
#define VVQ 32000
#define LLQ 3
#define R2F 0.70710678118654752440f

// ---------------- scratch (single __device__ array, no allocs) ----------------
__device__ float g_scratch[25690112];

// ---------------- tf32 tensor-core batched GEMM ----------------
// C[bz][m][n] = epilogue( sum_k A[bz*a_b + m*a_sm + k*a_sk] * B[bz*b_b + k*b_sk + n*b_sn] + bias )
// SPLITS: 3 = 3xTF32 (fp32-class accuracy), 1 = plain tf32
struct GemmP {
    const float* A; long long a_sm, a_sk, a_b;
    const float* Bm; long long b_sk, b_sn, b_b;
    float* C; long long c_row, c_b;
    const float* bias; int bias_per_m;
    int M, N, K, mode;           // mode: 0 plain, 1 enc-out (pad zero + combined), 2 (+emb)*R2
    const int* tokens;
    const float* emb; long long emb_b;
    float* C2;
};

__device__ __forceinline__ unsigned f2tf(float x) {
    unsigned r;
    asm("cvt.rna.tf32.f32 %0, %1;" : "=r"(r) : "f"(x));
    return r;
}

__device__ __forceinline__ void mma8(float* d, const unsigned* a, const unsigned* b) {
    asm volatile(
        "mma.sync.aligned.m16n8k8.row.col.f32.tf32.tf32.f32 "
        "{%0,%1,%2,%3}, {%4,%5,%6,%7}, {%8,%9}, {%0,%1,%2,%3};"
        : "+f"(d[0]), "+f"(d[1]), "+f"(d[2]), "+f"(d[3])
        : "r"(a[0]), "r"(a[1]), "r"(a[2]), "r"(a[3]), "r"(b[0]), "r"(b[1]));
}

template <int SPLITS>
__global__ __launch_bounds__(256) void tgemm_kernel(GemmP p) {
    __shared__ float As[32][136];
    __shared__ float Bs[32][136];
    int bz = blockIdx.z;
    long long Abase = (long long)bz * p.a_b;
    long long Bbase = (long long)bz * p.b_b;
    int m0 = blockIdx.y * 128, n0 = blockIdx.x * 128;
    int tid = threadIdx.x;
    int warp = tid >> 5, lane = tid & 31;
    int wm = warp >> 2, wn = warp & 3;   // warp tile: 64(m) x 32(n)
    int tig = lane & 3, grp = lane >> 2;

    float acc[4][4][4];
#pragma unroll
    for (int i = 0; i < 4; i++)
#pragma unroll
        for (int j = 0; j < 4; j++)
#pragma unroll
            for (int r = 0; r < 4; r++) acc[i][j][r] = 0.f;

    for (int k0 = 0; k0 < p.K; k0 += 32) {
        // ---- load A tile [128m x 32k] ----
        if (p.a_sk == 1) {
            int mm = tid >> 1, kb = (tid & 1) << 4;
            const float* Ap = p.A + Abase + (long long)(m0 + mm) * p.a_sm + k0 + kb;
#pragma unroll
            for (int u = 0; u < 4; u++) {
                float4 v = *(const float4*)(Ap + u * 4);
                As[kb + u * 4 + 0][mm] = v.x;
                As[kb + u * 4 + 1][mm] = v.y;
                As[kb + u * 4 + 2][mm] = v.z;
                As[kb + u * 4 + 3][mm] = v.w;
            }
        } else {
#pragma unroll
            for (int q = 0; q < 16; q++) {
                int j = tid + q * 256;
                int mm = j & 127, kk = j >> 7;
                As[kk][mm] = p.A[Abase + (long long)(m0 + mm) * p.a_sm + (long long)(k0 + kk) * p.a_sk];
            }
        }
        // ---- load B tile [32k x 128n] ----
        if (p.b_sk == 1) {
            int nn = tid >> 1, kb = (tid & 1) << 4;
            const float* Bp = p.Bm + Bbase + (long long)(n0 + nn) * p.b_sn + k0 + kb;
#pragma unroll
            for (int u = 0; u < 4; u++) {
                float4 v = *(const float4*)(Bp + u * 4);
                Bs[kb + u * 4 + 0][nn] = v.x;
                Bs[kb + u * 4 + 1][nn] = v.y;
                Bs[kb + u * 4 + 2][nn] = v.z;
                Bs[kb + u * 4 + 3][nn] = v.w;
            }
        } else {
#pragma unroll
            for (int q = 0; q < 16; q++) {
                int j = tid + q * 256;
                int nn = j & 127, kk = j >> 7;
                Bs[kk][nn] = p.Bm[Bbase + (long long)(k0 + kk) * p.b_sk + (long long)(n0 + nn) * p.b_sn];
            }
        }
        __syncthreads();

#pragma unroll
        for (int ks = 0; ks < 32; ks += 8) {
            unsigned ah[4][4], al[4][4], bh[4][2], bl[4][2];
#pragma unroll
            for (int mf = 0; mf < 4; mf++) {
                int mr = wm * 64 + mf * 16 + grp;
                float f0 = As[ks + tig][mr];
                float f1 = As[ks + tig][mr + 8];
                float f2 = As[ks + tig + 4][mr];
                float f3 = As[ks + tig + 4][mr + 8];
                ah[mf][0] = f2tf(f0);
                ah[mf][1] = f2tf(f1);
                ah[mf][2] = f2tf(f2);
                ah[mf][3] = f2tf(f3);
                if (SPLITS == 3) {
                    al[mf][0] = f2tf(f0 - __uint_as_float(ah[mf][0]));
                    al[mf][1] = f2tf(f1 - __uint_as_float(ah[mf][1]));
                    al[mf][2] = f2tf(f2 - __uint_as_float(ah[mf][2]));
                    al[mf][3] = f2tf(f3 - __uint_as_float(ah[mf][3]));
                }
            }
#pragma unroll
            for (int nf = 0; nf < 4; nf++) {
                int nc = wn * 32 + nf * 8 + grp;
                float g0 = Bs[ks + tig][nc];
                float g1 = Bs[ks + tig + 4][nc];
                bh[nf][0] = f2tf(g0);
                bh[nf][1] = f2tf(g1);
                if (SPLITS == 3) {
                    bl[nf][0] = f2tf(g0 - __uint_as_float(bh[nf][0]));
                    bl[nf][1] = f2tf(g1 - __uint_as_float(bh[nf][1]));
                }
            }
#pragma unroll
            for (int mf = 0; mf < 4; mf++)
#pragma unroll
                for (int nf = 0; nf < 4; nf++) {
                    mma8(acc[mf][nf], ah[mf], bh[nf]);
                    if (SPLITS == 3) {
                        mma8(acc[mf][nf], ah[mf], bl[nf]);
                        mma8(acc[mf][nf], al[mf], bh[nf]);
                    }
                }
        }
        __syncthreads();
    }

    // ---- epilogue ----
#pragma unroll
    for (int mf = 0; mf < 4; mf++) {
#pragma unroll
        for (int nf = 0; nf < 4; nf++) {
#pragma unroll
            for (int half = 0; half < 2; half++) {
                int m = m0 + wm * 64 + mf * 16 + grp + half * 8;
                int n = n0 + wn * 32 + nf * 8 + tig * 2;
                float v0 = acc[mf][nf][half * 2 + 0];
                float v1 = acc[mf][nf][half * 2 + 1];
                if (p.bias) {
                    if (p.bias_per_m) { float bm = p.bias[m]; v0 += bm; v1 += bm; }
                    else { v0 += p.bias[n]; v1 += p.bias[n + 1]; }
                }
                long long cidx = (long long)bz * p.c_b + (long long)m * p.c_row + n;
                if (p.mode == 0) {
                    *(float2*)&p.C[cidx] = make_float2(v0, v1);
                } else if (p.mode == 1) {
                    int tok = p.tokens[bz * SSQ + m];
                    if (tok == 0) { v0 = 0.f; v1 = 0.f; }
                    *(float2*)&p.C[cidx] = make_float2(v0, v1);
                    float2 e = *(const float2*)&p.emb[(long long)bz * p.emb_b + (long long)m * p.N + n];
                    *(float2*)&p.C2[cidx] = make_float2((v0 + e.x) * R2F, (v1 + e.y) * R2F);
                } else {
                    float2 e = *(const float2*)&p.emb[(long long)bz * p.emb_b + (long long)m * p.N + n];
                    *(float2*)&p.C[cidx] = make_float2((v0 + e.x) * R2F, (v1 + e.y) * R2F);
                }
            }
        }
    }
}

// ---------------- embeddings ----------------
__global__ void embed_kernel(const int* __restrict__ tokens, const float* __restrict__ tok_emb,
                             const float* __restrict__ pos_emb, float* __restrict__ out, int Slen) {
    int b = blockIdx.y;
    __shared__ int pos[SSQ];
    if (threadIdx.x == 0) {
        int c = 0;
        for (int s = 0; s < Slen; s++) {
            int m = (tokens[b * Slen + s] != 0) ? 1 : 0;
            c += m;
            pos[s] = c * m;
        }
    }
    __syncthreads();
    int chunk = Slen / gridDim.x;
    int s0 = blockIdx.x * chunk;
    for (int idx = threadIdx.x; idx < chunk * DDQ; idx += blockDim.x) {
        int s = s0 + idx / DDQ;
        int d = idx % DDQ;
        int tk = tokens[b * Slen + s];
        out[((long long)b * Slen + s) * DDQ + d] =
            tok_emb[(long long)tk * DDQ + d] + pos_emb[(long long)pos[s] * DDQ + d];
    }
}

// ---------------- im2col (row order ic*3+k so weights are contiguous) ----------------
__global__ void im2col_enc_kernel(const float* __restrict__ x, const int* __restrict__ tokens,
                                  float* __restrict__ out, int total) {
    int idx = blockIdx.x * blockDim.x + threadIdx.x;
    if (idx >= total) return;
    int s = idx % SSQ;
    int r = (idx / SSQ) % (3 * DDQ);
    int b = idx / (SSQ * 3 * DDQ);
    int ic = r / 3, k = r % 3;
    int s2 = s + k - 1;
    float v = 0.f;
    if (s2 >= 0 && s2 < SSQ && tokens[b * SSQ + s2] != 0)
        v = x[((long long)b * DDQ + ic) * SSQ + s2];
    out[idx] = v;
}

__global__ void im2col_dec_kernel(const float* __restrict__ x, float* __restrict__ out, int total) {
    int idx = blockIdx.x * blockDim.x + threadIdx.x;
    if (idx >= total) return;
    int t = idx % TTQ;
    int r = (idx / TTQ) % (3 * DDQ);
    int b = idx / (TTQ * 3 * DDQ);
    int ic = r / 3, k = r % 3;
    int t2 = t + k - 2;  // causal: pad K-1=2 left
    out[idx] = (t2 >= 0) ? x[((long long)b * DDQ + ic) * TTQ + t2] : 0.f;
}

// ---------------- GLU (+ optional residual, in place on x) ----------------
__global__ void glu_res_kernel(const float* __restrict__ y, float* __restrict__ x,
                               int total, int DS, int apply_res) {
    int idx = blockIdx.x * blockDim.x + threadIdx.x;
    if (idx >= total) return;
    int b = idx / DS;
    int rem = idx - b * DS;
    float a = y[(long long)b * 2 * DS + rem];
    float g = y[(long long)b * 2 * DS + DS + rem];
    float v = a / (1.f + expf(-g));
    x[idx] = apply_res ? (v + x[idx]) * R2F : v;
}

// ---------------- decoder combine: x = ((c + att2^T)*R2 + x)*R2 ----------------
__global__ void dec_combine_kernel(float* __restrict__ x, const float* __restrict__ c,
                                   const float* __restrict__ att2, int total) {
    int idx = blockIdx.x * blockDim.x + threadIdx.x;
    if (idx >= total) return;
    int b = idx / (DDQ * TTQ);
    int rem = idx - b * (DDQ * TTQ);
    int ch = rem / TTQ;
    int t = rem % TTQ;
    float cc = (c[idx] + att2[((long long)b * TTQ + t) * DDQ + ch]) * R2F;
    x[idx] = (cc + x[idx]) * R2F;
}

// ---------------- masked softmax over S ----------------
__global__ void softmax_mask_kernel(float* __restrict__ energy, const int* __restrict__ src) {
    int row = blockIdx.x;           // b*T + t
    int b = row / TTQ;
    float* e = energy + (long long)row * SSQ;
    int s = threadIdx.x;            // 256 = S
    float v = (src[b * SSQ + s] == 0) ? -INFINITY : e[s];
    __shared__ float red[SSQ];
    red[s] = v;
    __syncthreads();
    for (int off = 128; off > 0; off >>= 1) {
        if (s < off) red[s] = fmaxf(red[s], red[s + off]);
        __syncthreads();
    }
    float mx = red[0];
    __syncthreads();
    float ex = expf(v - mx);
    red[s] = ex;
    __syncthreads();
    for (int off = 128; off > 0; off >>= 1) {
        if (s < off) red[s] += red[s + off];
        __syncthreads();
    }
    e[s] = ex / red[0];
}

// ---------------- host side ----------------
static void gemm(const float* A, long long a_sm, long long a_sk, long long a_b,
                 const float* Bm, long long b_sk, long long b_sn, long long b_b,
                 float* C, long long c_row, long long c_b,
                 const float* bias, int bias_per_m,
                 int M, int N, int K, int nb,
                 int mode = 0, const int* tokens = nullptr,
                 const float* emb = nullptr, long long emb_b = 0, float* C2 = nullptr,
                 int splits = 3) {
    GemmP p;
    p.A = A; p.a_sm = a_sm; p.a_sk = a_sk; p.a_b = a_b;
    p.Bm = Bm; p.b_sk = b_sk; p.b_sn = b_sn; p.b_b = b_b;
    p.C = C; p.c_row = c_row; p.c_b = c_b;
    p.bias = bias; p.bias_per_m = bias_per_m;
    p.M = M; p.N = N; p.K = K; p.mode = mode;
    p.tokens = tokens; p.emb = emb; p.emb_b = emb_b; p.C2 = C2;
    dim3 grid(N / 128, M / 128, nb);
    if (splits == 3) tgemm_kernel<3><<<grid, 256>>>(p);
    else             tgemm_kernel<1><<<grid, 256>>>(p);
}

extern "C" void kernel_launch(void* const* d_in, const int* in_sizes, int n_in,
                              void* d_out, int out_size) {
    const int*   src        = (const int*)d_in[0];
    const int*   trg        = (const int*)d_in[1];
    const float* enc_tok    = (const float*)d_in[2];
    const float* enc_pos    = (const float*)d_in[3];
    const float* dec_tok    = (const float*)d_in[4];
    const float* dec_pos    = (const float*)d_in[5];
    const float* enc_in_w   = (const float*)d_in[6];
    const float* enc_in_b   = (const float*)d_in[7];
    const float* enc_conv_w = (const float*)d_in[8];
    const float* enc_conv_b = (const float*)d_in[9];
    const float* enc_out_w  = (const float*)d_in[10];
    const float* enc_out_b  = (const float*)d_in[11];
    const float* dec_in_w   = (const float*)d_in[12];
    const float* dec_in_b   = (const float*)d_in[13];
    const float* dec_conv_w = (const float*)d_in[14];
    const float* dec_conv_b = (const float*)d_in[15];
    const float* attn_in_w  = (const float*)d_in[16];
    const float* attn_in_b  = (const float*)d_in[17];
    const float* attn_out_w = (const float*)d_in[18];
    const float* attn_out_b = (const float*)d_in[19];
    const float* dec_out_w  = (const float*)d_in[20];
    const float* dec_out_b  = (const float*)d_in[21];
    const float* vocab_w    = (const float*)d_in[22];
    const float* vocab_b    = (const float*)d_in[23];
    float* logits = (float*)d_out;

    void* sp;
    cudaGetSymbolAddress(&sp, g_scratch);
    float* base = (float*)sp;
    float* enc_emb    = base;
    float* enc_x      = base + 2097152;
    float* im2col     = base + 4194304;
    float* ybuf       = base + 10485760;
    float* enc_conved = base + 14680064;
    float* enc_comb   = base + 16777216;
    float* dec_emb    = base + 18874368;
    float* dec_x      = base + 19922944;
    float* dec_c      = base + 20971520;
    float* qbuf       = base + 22020096;
    float* energy     = base + 23068672;
    float* att        = base + 23592960;
    float* att2       = base + 24641536;

    // ---- embeddings ----
    embed_kernel<<<dim3(4, BB), 256>>>(src, enc_tok, enc_pos, enc_emb, SSQ);
    embed_kernel<<<dim3(4, BB), 256>>>(trg, dec_tok, dec_pos, dec_emb, TTQ);

    // ---- encoder in-projection -> x[b][c][s] ----
    gemm(enc_in_w, 1, DDQ, 0,
         enc_emb, 1, DDQ, (long long)SSQ * DDQ,
         enc_x, SSQ, (long long)DDQ * SSQ,
         enc_in_b, 1, DDQ, SSQ, DDQ, BB);

    // ---- encoder conv stack ----
    for (int l = 0; l < LLQ; l++) {
        int tot = BB * DDQ * 3 * SSQ;
        im2col_enc_kernel<<<(tot + 255) / 256, 256>>>(enc_x, src, im2col, tot);
        gemm(enc_conv_w + (long long)l * 2 * DDQ * DDQ * 3, 3 * DDQ, 1, 0,
             im2col, SSQ, 1, (long long)3 * DDQ * SSQ,
             ybuf, SSQ, (long long)2 * DDQ * SSQ,
             enc_conv_b + l * 2 * DDQ, 1, 2 * DDQ, SSQ, 3 * DDQ, BB);
        int tot2 = BB * DDQ * SSQ;
        glu_res_kernel<<<(tot2 + 255) / 256, 256>>>(ybuf, enc_x, tot2, DDQ * SSQ, 1);
    }

    // ---- encoder out-projection (+pad mask, combined) ----
    gemm(enc_x, 1, SSQ, (long long)DDQ * SSQ,
         enc_out_w, DDQ, 1, 0,
         enc_conved, DDQ, (long long)SSQ * DDQ,
         enc_out_b, 0, SSQ, DDQ, DDQ, BB,
         1, src, enc_emb, (long long)SSQ * DDQ, enc_comb);

    // ---- decoder in-projection -> x[b][c][t] ----
    gemm(dec_in_w, 1, DDQ, 0,
         dec_emb, 1, DDQ, (long long)TTQ * DDQ,
         dec_x, TTQ, (long long)DDQ * TTQ,
         dec_in_b, 1, DDQ, TTQ, DDQ, BB);

    // ---- decoder layers ----
    for (int l = 0; l < LLQ; l++) {
        int tot = BB * DDQ * 3 * TTQ;
        im2col_dec_kernel<<<(tot + 255) / 256, 256>>>(dec_x, im2col, tot);
        gemm(dec_conv_w + (long long)l * 2 * DDQ * DDQ * 3, 3 * DDQ, 1, 0,
             im2col, TTQ, 1, (long long)3 * DDQ * TTQ,
             ybuf, TTQ, (long long)2 * DDQ * TTQ,
             dec_conv_b + l * 2 * DDQ, 1, 2 * DDQ, TTQ, 3 * DDQ, BB);
        int tot2 = BB * DDQ * TTQ;
        glu_res_kernel<<<(tot2 + 255) / 256, 256>>>(ybuf, dec_c, tot2, DDQ * TTQ, 0);

        // q = (c^T @ Wq + bq + emb) * R2
        gemm(dec_c, 1, TTQ, (long long)DDQ * TTQ,
             attn_in_w + (long long)l * DDQ * DDQ, DDQ, 1, 0,
             qbuf, DDQ, (long long)TTQ * DDQ,
             attn_in_b + l * DDQ, 0, TTQ, DDQ, DDQ, BB,
             2, nullptr, dec_emb, (long long)TTQ * DDQ, nullptr);

        // energy = q @ enc_conved^T
        gemm(qbuf, DDQ, 1, (long long)TTQ * DDQ,
             enc_conved, 1, DDQ, (long long)SSQ * DDQ,
             energy, SSQ, (long long)TTQ * SSQ,
             nullptr, 0, TTQ, SSQ, DDQ, BB);

        softmax_mask_kernel<<<BB * TTQ, SSQ>>>(energy, src);

        // att = attn @ enc_combined
        gemm(energy, SSQ, 1, (long long)TTQ * SSQ,
             enc_comb, DDQ, 1, (long long)SSQ * DDQ,
             att, DDQ, (long long)TTQ * DDQ,
             nullptr, 0, TTQ, DDQ, SSQ, BB);

        // att2 = att @ Wout + bout
        gemm(att, DDQ, 1, 0,
             attn_out_w + (long long)l * DDQ * DDQ, DDQ, 1, 0,
             att2, DDQ, 0,
             attn_out_b + l * DDQ, 0, BB * TTQ, DDQ, DDQ, 1);

        int tot3 = BB * DDQ * TTQ;
        dec_combine_kernel<<<(tot3 + 255) / 256, 256>>>(dec_x, dec_c, att2, tot3);
    }

    // ---- decoder out-projection -> [B,T,D] (reuse qbuf) ----
    gemm(dec_x, 1, TTQ, (long long)DDQ * TTQ,
         dec_out_w, DDQ, 1, 0,
         qbuf, DDQ, (long long)TTQ * DDQ,
         dec_out_b, 0, TTQ, DDQ, DDQ, BB);

    // ---- vocab projection -> logits [B*T, V] (1x tf32: terminal op, error doesn't compound) ----
    gemm(qbuf, DDQ, 1, 0,
         vocab_w, VVQ, 1, 0,
         logits, VVQ, 0,
         vocab_b, 0, BB * TTQ, VVQ, DDQ, 1,
         0, nullptr, nullptr, 0, nullptr, 1);
}

// round 5
// speedup vs baseline: 1.8964x; 1.2025x over previous
#include <cuda_runtime.h>
#include <cuda_bf16.h>
#include <math.h>

#define BB 16
#define SSQ 256
#define TTQ 128
#define DDQ 512
#define VVQ 32000
#define LLQ 3
#define R2F 0.70710678118654752440f

// ---------------- scratch (single __device__ array, no allocs) ----------------
__device__ float g_scratch[25690112];

// ---------------- bf16 split-pair tensor-core batched GEMM ----------------
// C[bz][m][n] = epilogue( sum_k A[..] * B[..] + bias ), fp32-class accuracy via
// x = hi + lo (bf16 each); product = hi*hi + hi*lo + lo*hi (drop lo*lo ~2^-18).
struct GemmP {
    const float* A; long long a_sm, a_sk, a_b;
    const float* Bm; long long b_sk, b_sn, b_b;
    float* C; long long c_row, c_b;
    const float* bias; int bias_per_m;
    int M, N, K, mode;           // mode: 0 plain, 1 enc-out (pad zero + combined), 2 (+emb)*R2
    const int* tokens;
    const float* emb; long long emb_b;
    float* C2;
};

__device__ __forceinline__ void cvt_pair(float x0, float x1, unsigned& hw, unsigned& lw) {
    __nv_bfloat162 h = __floats2bfloat162_rn(x0, x1);
    float2 hf = __bfloat1622float2(h);
    __nv_bfloat162 l = __floats2bfloat162_rn(x0 - hf.x, x1 - hf.y);
    hw = *reinterpret_cast<unsigned*>(&h);
    lw = *reinterpret_cast<unsigned*>(&l);
}

__device__ __forceinline__ void mma16(float* d, const unsigned* a, const unsigned* b) {
    asm volatile(
        "mma.sync.aligned.m16n8k16.row.col.f32.bf16.bf16.f32 "
        "{%0,%1,%2,%3}, {%4,%5,%6,%7}, {%8,%9}, {%0,%1,%2,%3};"
        : "+f"(d[0]), "+f"(d[1]), "+f"(d[2]), "+f"(d[3])
        : "r"(a[0]), "r"(a[1]), "r"(a[2]), "r"(a[3]), "r"(b[0]), "r"(b[1]));
}

__global__ __launch_bounds__(256) void tgemm_kernel(GemmP p) {
    // packed bf16x2 planes: [k/2][m or n], stride 136 words -> conflict-free LDS & STS
    __shared__ unsigned Ah[16][136], Al[16][136];
    __shared__ unsigned Bh[16][136], Bl[16][136];
    int bz = blockIdx.z;
    long long Abase = (long long)bz * p.a_b;
    long long Bbase = (long long)bz * p.b_b;
    int m0 = blockIdx.y * 128, n0 = blockIdx.x * 128;
    int tid = threadIdx.x;
    int warp = tid >> 5, lane = tid & 31;
    int wm = warp >> 2, wn = warp & 3;   // warp tile: 64(m) x 32(n)
    int tig = lane & 3, grp = lane >> 2;

    float acc[4][4][4];
#pragma unroll
    for (int i = 0; i < 4; i++)
#pragma unroll
        for (int j = 0; j < 4; j++)
#pragma unroll
            for (int r = 0; r < 4; r++) acc[i][j][r] = 0.f;

    for (int k0 = 0; k0 < p.K; k0 += 32) {
        // ---- load + convert A tile [128m x 32k] ----
        if (p.a_sk == 1) {
            int mm = tid >> 1, kb = (tid & 1) << 4, kb2 = (tid & 1) << 3;
            const float* Ap = p.A + Abase + (long long)(m0 + mm) * p.a_sm + k0 + kb;
#pragma unroll
            for (int u = 0; u < 4; u++) {
                float4 v = *(const float4*)(Ap + u * 4);
                cvt_pair(v.x, v.y, Ah[kb2 + u * 2][mm], Al[kb2 + u * 2][mm]);
                cvt_pair(v.z, v.w, Ah[kb2 + u * 2 + 1][mm], Al[kb2 + u * 2 + 1][mm]);
            }
        } else {
#pragma unroll
            for (int q = 0; q < 8; q++) {
                int j = tid + q * 256;
                int mm = j & 127, k2 = j >> 7;
                long long base = Abase + (long long)(m0 + mm) * p.a_sm;
                float x0 = p.A[base + (long long)(k0 + 2 * k2) * p.a_sk];
                float x1 = p.A[base + (long long)(k0 + 2 * k2 + 1) * p.a_sk];
                cvt_pair(x0, x1, Ah[k2][mm], Al[k2][mm]);
            }
        }
        // ---- load + convert B tile [32k x 128n] ----
        if (p.b_sk == 1) {
            int nn = tid >> 1, kb = (tid & 1) << 4, kb2 = (tid & 1) << 3;
            const float* Bp = p.Bm + Bbase + (long long)(n0 + nn) * p.b_sn + k0 + kb;
#pragma unroll
            for (int u = 0; u < 4; u++) {
                float4 v = *(const float4*)(Bp + u * 4);
                cvt_pair(v.x, v.y, Bh[kb2 + u * 2][nn], Bl[kb2 + u * 2][nn]);
                cvt_pair(v.z, v.w, Bh[kb2 + u * 2 + 1][nn], Bl[kb2 + u * 2 + 1][nn]);
            }
        } else {
#pragma unroll
            for (int q = 0; q < 8; q++) {
                int j = tid + q * 256;
                int nn = j & 127, k2 = j >> 7;
                long long base = Bbase + (long long)(n0 + nn) * p.b_sn;
                float x0 = p.Bm[base + (long long)(k0 + 2 * k2) * p.b_sk];
                float x1 = p.Bm[base + (long long)(k0 + 2 * k2 + 1) * p.b_sk];
                cvt_pair(x0, x1, Bh[k2][nn], Bl[k2][nn]);
            }
        }
        __syncthreads();

#pragma unroll
        for (int kc2 = 0; kc2 < 16; kc2 += 8) {  // two k16 chunks per 32-k tile
            unsigned ah[4][4], al[4][4], bh[4][2], bl[4][2];
#pragma unroll
            for (int mf = 0; mf < 4; mf++) {
                int mr = wm * 64 + mf * 16 + grp;
                ah[mf][0] = Ah[kc2 + tig][mr];
                ah[mf][1] = Ah[kc2 + tig][mr + 8];
                ah[mf][2] = Ah[kc2 + tig + 4][mr];
                ah[mf][3] = Ah[kc2 + tig + 4][mr + 8];
                al[mf][0] = Al[kc2 + tig][mr];
                al[mf][1] = Al[kc2 + tig][mr + 8];
                al[mf][2] = Al[kc2 + tig + 4][mr];
                al[mf][3] = Al[kc2 + tig + 4][mr + 8];
            }
#pragma unroll
            for (int nf = 0; nf < 4; nf++) {
                int nc = wn * 32 + nf * 8 + grp;
                bh[nf][0] = Bh[kc2 + tig][nc];
                bh[nf][1] = Bh[kc2 + tig + 4][nc];
                bl[nf][0] = Bl[kc2 + tig][nc];
                bl[nf][1] = Bl[kc2 + tig + 4][nc];
            }
#pragma unroll
            for (int mf = 0; mf < 4; mf++)
#pragma unroll
                for (int nf = 0; nf < 4; nf++) {
                    mma16(acc[mf][nf], ah[mf], bh[nf]);
                    mma16(acc[mf][nf], ah[mf], bl[nf]);
                    mma16(acc[mf][nf], al[mf], bh[nf]);
                }
        }
        __syncthreads();
    }

    // ---- epilogue ----
#pragma unroll
    for (int mf = 0; mf < 4; mf++) {
#pragma unroll
        for (int nf = 0; nf < 4; nf++) {
#pragma unroll
            for (int half = 0; half < 2; half++) {
                int m = m0 + wm * 64 + mf * 16 + grp + half * 8;
                int n = n0 + wn * 32 + nf * 8 + tig * 2;
                float v0 = acc[mf][nf][half * 2 + 0];
                float v1 = acc[mf][nf][half * 2 + 1];
                if (p.bias) {
                    if (p.bias_per_m) { float bm = p.bias[m]; v0 += bm; v1 += bm; }
                    else { v0 += p.bias[n]; v1 += p.bias[n + 1]; }
                }
                long long cidx = (long long)bz * p.c_b + (long long)m * p.c_row + n;
                if (p.mode == 0) {
                    *(float2*)&p.C[cidx] = make_float2(v0, v1);
                } else if (p.mode == 1) {
                    int tok = p.tokens[bz * SSQ + m];
                    if (tok == 0) { v0 = 0.f; v1 = 0.f; }
                    *(float2*)&p.C[cidx] = make_float2(v0, v1);
                    float2 e = *(const float2*)&p.emb[(long long)bz * p.emb_b + (long long)m * p.N + n];
                    *(float2*)&p.C2[cidx] = make_float2((v0 + e.x) * R2F, (v1 + e.y) * R2F);
                } else {
                    float2 e = *(const float2*)&p.emb[(long long)bz * p.emb_b + (long long)m * p.N + n];
                    *(float2*)&p.C[cidx] = make_float2((v0 + e.x) * R2F, (v1 + e.y) * R2F);
                }
            }
        }
    }
}

// ---------------- embeddings ----------------
__global__ void embed_kernel(const int* __restrict__ tokens, const float* __restrict__ tok_emb,
                             const float* __restrict__ pos_emb, float* __restrict__ out, int Slen) {
    int b = blockIdx.y;
    __shared__ int pos[SSQ];
    if (threadIdx.x == 0) {
        int c = 0;
        for (int s = 0; s < Slen; s++) {
            int m = (tokens[b * Slen + s] != 0) ? 1 : 0;
            c += m;
            pos[s] = c * m;
        }
    }
    __syncthreads();
    int chunk = Slen / gridDim.x;
    int s0 = blockIdx.x * chunk;
    for (int idx = threadIdx.x; idx < chunk * DDQ; idx += blockDim.x) {
        int s = s0 + idx / DDQ;
        int d = idx % DDQ;
        int tk = tokens[b * Slen + s];
        out[((long long)b * Slen + s) * DDQ + d] =
            tok_emb[(long long)tk * DDQ + d] + pos_emb[(long long)pos[s] * DDQ + d];
    }
}

// ---------------- im2col (row order ic*3+k so weights are contiguous) ----------------
__global__ void im2col_enc_kernel(const float* __restrict__ x, const int* __restrict__ tokens,
                                  float* __restrict__ out, int total) {
    int idx = blockIdx.x * blockDim.x + threadIdx.x;
    if (idx >= total) return;
    int s = idx % SSQ;
    int r = (idx / SSQ) % (3 * DDQ);
    int b = idx / (SSQ * 3 * DDQ);
    int ic = r / 3, k = r % 3;
    int s2 = s + k - 1;
    float v = 0.f;
    if (s2 >= 0 && s2 < SSQ && tokens[b * SSQ + s2] != 0)
        v = x[((long long)b * DDQ + ic) * SSQ + s2];
    out[idx] = v;
}

__global__ void im2col_dec_kernel(const float* __restrict__ x, float* __restrict__ out, int total) {
    int idx = blockIdx.x * blockDim.x + threadIdx.x;
    if (idx >= total) return;
    int t = idx % TTQ;
    int r = (idx / TTQ) % (3 * DDQ);
    int b = idx / (TTQ * 3 * DDQ);
    int ic = r / 3, k = r % 3;
    int t2 = t + k - 2;  // causal: pad K-1=2 left
    out[idx] = (t2 >= 0) ? x[((long long)b * DDQ + ic) * TTQ + t2] : 0.f;
}

// ---------------- GLU (+ optional residual, in place on x) ----------------
__global__ void glu_res_kernel(const float* __restrict__ y, float* __restrict__ x,
                               int total, int DS, int apply_res) {
    int idx = blockIdx.x * blockDim.x + threadIdx.x;
    if (idx >= total) return;
    int b = idx / DS;
    int rem = idx - b * DS;
    float a = y[(long long)b * 2 * DS + rem];
    float g = y[(long long)b * 2 * DS + DS + rem];
    float v = a / (1.f + expf(-g));
    x[idx] = apply_res ? (v + x[idx]) * R2F : v;
}

// ---------------- decoder combine: x = ((c + att2^T)*R2 + x)*R2 ----------------
__global__ void dec_combine_kernel(float* __restrict__ x, const float* __restrict__ c,
                                   const float* __restrict__ att2, int total) {
    int idx = blockIdx.x * blockDim.x + threadIdx.x;
    if (idx >= total) return;
    int b = idx / (DDQ * TTQ);
    int rem = idx - b * (DDQ * TTQ);
    int ch = rem / TTQ;
    int t = rem % TTQ;
    float cc = (c[idx] + att2[((long long)b * TTQ + t) * DDQ + ch]) * R2F;
    x[idx] = (cc + x[idx]) * R2F;
}

// ---------------- masked softmax over S ----------------
__global__ void softmax_mask_kernel(float* __restrict__ energy, const int* __restrict__ src) {
    int row = blockIdx.x;           // b*T + t
    int b = row / TTQ;
    float* e = energy + (long long)row * SSQ;
    int s = threadIdx.x;            // 256 = S
    float v = (src[b * SSQ + s] == 0) ? -INFINITY : e[s];
    __shared__ float red[SSQ];
    red[s] = v;
    __syncthreads();
    for (int off = 128; off > 0; off >>= 1) {
        if (s < off) red[s] = fmaxf(red[s], red[s + off]);
        __syncthreads();
    }
    float mx = red[0];
    __syncthreads();
    float ex = expf(v - mx);
    red[s] = ex;
    __syncthreads();
    for (int off = 128; off > 0; off >>= 1) {
        if (s < off) red[s] += red[s + off];
        __syncthreads();
    }
    e[s] = ex / red[0];
}

// ---------------- host side ----------------
static void gemm(const float* A, long long a_sm, long long a_sk, long long a_b,
                 const float* Bm, long long b_sk, long long b_sn, long long b_b,
                 float* C, long long c_row, long long c_b,
                 const float* bias, int bias_per_m,
                 int M, int N, int K, int nb,
                 int mode = 0, const int* tokens = nullptr,
                 const float* emb = nullptr, long long emb_b = 0, float* C2 = nullptr) {
    GemmP p;
    p.A = A; p.a_sm = a_sm; p.a_sk = a_sk; p.a_b = a_b;
    p.Bm = Bm; p.b_sk = b_sk; p.b_sn = b_sn; p.b_b = b_b;
    p.C = C; p.c_row = c_row; p.c_b = c_b;
    p.bias = bias; p.bias_per_m = bias_per_m;
    p.M = M; p.N = N; p.K = K; p.mode = mode;
    p.tokens = tokens; p.emb = emb; p.emb_b = emb_b; p.C2 = C2;
    dim3 grid(N / 128, M / 128, nb);
    tgemm_kernel<<<grid, 256>>>(p);
}

extern "C" void kernel_launch(void* const* d_in, const int* in_sizes, int n_in,
                              void* d_out, int out_size) {
    const int*   src        = (const int*)d_in[0];
    const int*   trg        = (const int*)d_in[1];
    const float* enc_tok    = (const float*)d_in[2];
    const float* enc_pos    = (const float*)d_in[3];
    const float* dec_tok    = (const float*)d_in[4];
    const float* dec_pos    = (const float*)d_in[5];
    const float* enc_in_w   = (const float*)d_in[6];
    const float* enc_in_b   = (const float*)d_in[7];
    const float* enc_conv_w = (const float*)d_in[8];
    const float* enc_conv_b = (const float*)d_in[9];
    const float* enc_out_w  = (const float*)d_in[10];
    const float* enc_out_b  = (const float*)d_in[11];
    const float* dec_in_w   = (const float*)d_in[12];
    const float* dec_in_b   = (const float*)d_in[13];
    const float* dec_conv_w = (const float*)d_in[14];
    const float* dec_conv_b = (const float*)d_in[15];
    const float* attn_in_w  = (const float*)d_in[16];
    const float* attn_in_b  = (const float*)d_in[17];
    const float* attn_out_w = (const float*)d_in[18];
    const float* attn_out_b = (const float*)d_in[19];
    const float* dec_out_w  = (const float*)d_in[20];
    const float* dec_out_b  = (const float*)d_in[21];
    const float* vocab_w    = (const float*)d_in[22];
    const float* vocab_b    = (const float*)d_in[23];
    float* logits = (float*)d_out;

    void* sp;
    cudaGetSymbolAddress(&sp, g_scratch);
    float* base = (float*)sp;
    float* enc_emb    = base;
    float* enc_x      = base + 2097152;
    float* im2col     = base + 4194304;
    float* ybuf       = base + 10485760;
    float* enc_conved = base + 14680064;
    float* enc_comb   = base + 16777216;
    float* dec_emb    = base + 18874368;
    float* dec_x      = base + 19922944;
    float* dec_c      = base + 20971520;
    float* qbuf       = base + 22020096;
    float* energy     = base + 23068672;
    float* att        = base + 23592960;
    float* att2       = base + 24641536;

    // ---- embeddings ----
    embed_kernel<<<dim3(4, BB), 256>>>(src, enc_tok, enc_pos, enc_emb, SSQ);
    embed_kernel<<<dim3(4, BB), 256>>>(trg, dec_tok, dec_pos, dec_emb, TTQ);

    // ---- encoder in-projection -> x[b][c][s] ----
    gemm(enc_in_w, 1, DDQ, 0,
         enc_emb, 1, DDQ, (long long)SSQ * DDQ,
         enc_x, SSQ, (long long)DDQ * SSQ,
         enc_in_b, 1, DDQ, SSQ, DDQ, BB);

    // ---- encoder conv stack ----
    for (int l = 0; l < LLQ; l++) {
        int tot = BB * DDQ * 3 * SSQ;
        im2col_enc_kernel<<<(tot + 255) / 256, 256>>>(enc_x, src, im2col, tot);
        gemm(enc_conv_w + (long long)l * 2 * DDQ * DDQ * 3, 3 * DDQ, 1, 0,
             im2col, SSQ, 1, (long long)3 * DDQ * SSQ,
             ybuf, SSQ, (long long)2 * DDQ * SSQ,
             enc_conv_b + l * 2 * DDQ, 1, 2 * DDQ, SSQ, 3 * DDQ, BB);
        int tot2 = BB * DDQ * SSQ;
        glu_res_kernel<<<(tot2 + 255) / 256, 256>>>(ybuf, enc_x, tot2, DDQ * SSQ, 1);
    }

    // ---- encoder out-projection (+pad mask, combined) ----
    gemm(enc_x, 1, SSQ, (long long)DDQ * SSQ,
         enc_out_w, DDQ, 1, 0,
         enc_conved, DDQ, (long long)SSQ * DDQ,
         enc_out_b, 0, SSQ, DDQ, DDQ, BB,
         1, src, enc_emb, (long long)SSQ * DDQ, enc_comb);

    // ---- decoder in-projection -> x[b][c][t] ----
    gemm(dec_in_w, 1, DDQ, 0,
         dec_emb, 1, DDQ, (long long)TTQ * DDQ,
         dec_x, TTQ, (long long)DDQ * TTQ,
         dec_in_b, 1, DDQ, TTQ, DDQ, BB);

    // ---- decoder layers ----
    for (int l = 0; l < LLQ; l++) {
        int tot = BB * DDQ * 3 * TTQ;
        im2col_dec_kernel<<<(tot + 255) / 256, 256>>>(dec_x, im2col, tot);
        gemm(dec_conv_w + (long long)l * 2 * DDQ * DDQ * 3, 3 * DDQ, 1, 0,
             im2col, TTQ, 1, (long long)3 * DDQ * TTQ,
             ybuf, TTQ, (long long)2 * DDQ * TTQ,
             dec_conv_b + l * 2 * DDQ, 1, 2 * DDQ, TTQ, 3 * DDQ, BB);
        int tot2 = BB * DDQ * TTQ;
        glu_res_kernel<<<(tot2 + 255) / 256, 256>>>(ybuf, dec_c, tot2, DDQ * TTQ, 0);

        // q = (c^T @ Wq + bq + emb) * R2
        gemm(dec_c, 1, TTQ, (long long)DDQ * TTQ,
             attn_in_w + (long long)l * DDQ * DDQ, DDQ, 1, 0,
             qbuf, DDQ, (long long)TTQ * DDQ,
             attn_in_b + l * DDQ, 0, TTQ, DDQ, DDQ, BB,
             2, nullptr, dec_emb, (long long)TTQ * DDQ, nullptr);

        // energy = q @ enc_conved^T
        gemm(qbuf, DDQ, 1, (long long)TTQ * DDQ,
             enc_conved, 1, DDQ, (long long)SSQ * DDQ,
             energy, SSQ, (long long)TTQ * SSQ,
             nullptr, 0, TTQ, SSQ, DDQ, BB);

        softmax_mask_kernel<<<BB * TTQ, SSQ>>>(energy, src);

        // att = attn @ enc_combined
        gemm(energy, SSQ, 1, (long long)TTQ * SSQ,
             enc_comb, DDQ, 1, (long long)SSQ * DDQ,
             att, DDQ, (long long)TTQ * DDQ,
             nullptr, 0, TTQ, DDQ, SSQ, BB);

        // att2 = att @ Wout + bout
        gemm(att, DDQ, 1, 0,
             attn_out_w + (long long)l * DDQ * DDQ, DDQ, 1, 0,
             att2, DDQ, 0,
             attn_out_b + l * DDQ, 0, BB * TTQ, DDQ, DDQ, 1);

        int tot3 = BB * DDQ * TTQ;
        dec_combine_kernel<<<(tot3 + 255) / 256, 256>>>(dec_x, dec_c, att2, tot3);
    }

    // ---- decoder out-projection -> [B,T,D] (reuse qbuf) ----
    gemm(dec_x, 1, TTQ, (long long)DDQ * TTQ,
         dec_out_w, DDQ, 1, 0,
         qbuf, DDQ, (long long)TTQ * DDQ,
         dec_out_b, 0, TTQ, DDQ, DDQ, BB);

    // ---- vocab projection -> logits [B*T, V] ----
    gemm(qbuf, DDQ, 1, 0,
         vocab_w, VVQ, 1, 0,
         logits, VVQ, 0,
         vocab_b, 0, BB * TTQ, VVQ, DDQ, 1);
}

// round 7
// speedup vs baseline: 2.6499x; 1.3973x over previous
#include <cuda_runtime.h>
#include <cuda_bf16.h>
#include <math.h>

#define BB 16
#define SSQ 256
#define TTQ 128
#define DDQ 512
#define VVQ 32000
#define LLQ 3
#define R2F 0.70710678118654752440f

// ---------------- scratch (single __device__ array, no allocs) ----------------
__device__ float g_scratch[25690112];

// ---------------- bf16 split-pair tensor-core batched GEMM (pipelined) ----------------
struct GemmP {
    const float* A; long long a_sm, a_sk, a_b;
    const float* Bm; long long b_sk, b_sn, b_b;
    float* C; long long c_row, c_b;
    const float* bias; int bias_per_m;
    int M, N, K, mode;           // mode: 0 plain, 1 enc-out (pad zero + combined), 2 (+emb)*R2
    const int* tokens;
    const float* emb; long long emb_b;
    float* C2;
};

__device__ __forceinline__ unsigned f2tf(float x) {
    unsigned r;
    asm("cvt.rna.tf32.f32 %0, %1;" : "=r"(r) : "f"(x));
    return r;
}

__device__ __forceinline__ void cvt_pair(float x0, float x1, unsigned& hw, unsigned& lw) {
    __nv_bfloat162 h = __floats2bfloat162_rn(x0, x1);
    float2 hf = __bfloat1622float2(h);
    __nv_bfloat162 l = __floats2bfloat162_rn(x0 - hf.x, x1 - hf.y);
    hw = *reinterpret_cast<unsigned*>(&h);
    lw = *reinterpret_cast<unsigned*>(&l);
}

__device__ __forceinline__ void mma16(float* d, const unsigned* a, const unsigned* b) {
    asm volatile(
        "mma.sync.aligned.m16n8k16.row.col.f32.bf16.bf16.f32 "
        "{%0,%1,%2,%3}, {%4,%5,%6,%7}, {%8,%9}, {%0,%1,%2,%3};"
        : "+f"(d[0]), "+f"(d[1]), "+f"(d[2]), "+f"(d[3])
        : "r"(a[0]), "r"(a[1]), "r"(a[2]), "r"(a[3]), "r"(b[0]), "r"(b[1]));
}

__device__ __forceinline__ void mma8(float* d, const unsigned* a, const unsigned* b) {
    asm volatile(
        "mma.sync.aligned.m16n8k8.row.col.f32.tf32.tf32.f32 "
        "{%0,%1,%2,%3}, {%4,%5,%6,%7}, {%8,%9}, {%0,%1,%2,%3};"
        : "+f"(d[0]), "+f"(d[1]), "+f"(d[2]), "+f"(d[3])
        : "r"(a[0]), "r"(a[1]), "r"(a[2]), "r"(a[3]), "r"(b[0]), "r"(b[1]));
}

// Load one 128(mn) x 32(k) tile into 16 staging regs per thread.
__device__ __forceinline__ void load_tile(const float* P, long long base, long long s_mn,
                                          long long s_k, int mn0, int k0, int tid, float* r) {
    if (s_k == 1) {
        int mm = tid >> 1, kb = (tid & 1) << 4;
        const float* p = P + base + (long long)(mn0 + mm) * s_mn + k0 + kb;
#pragma unroll
        for (int u = 0; u < 4; u++) {
            float4 v = *(const float4*)(p + u * 4);
            r[u * 4 + 0] = v.x; r[u * 4 + 1] = v.y; r[u * 4 + 2] = v.z; r[u * 4 + 3] = v.w;
        }
    } else {
#pragma unroll
        for (int q = 0; q < 8; q++) {
            int j = tid + q * 256;
            int mm = j & 127, k2 = j >> 7;
            long long b2 = base + (long long)(mn0 + mm) * s_mn;
            r[q * 2]     = P[b2 + (long long)(k0 + 2 * k2) * s_k];
            r[q * 2 + 1] = P[b2 + (long long)(k0 + 2 * k2 + 1) * s_k];
        }
    }
}

__device__ __forceinline__ void sts_tile(unsigned H[16][136], unsigned L[16][136],
                                         long long s_k, int tid, const float* r) {
    if (s_k == 1) {
        int mm = tid >> 1, kb2 = (tid & 1) << 3;
#pragma unroll
        for (int u = 0; u < 8; u++)
            cvt_pair(r[u * 2], r[u * 2 + 1], H[kb2 + u][mm], L[kb2 + u][mm]);
    } else {
#pragma unroll
        for (int q = 0; q < 8; q++) {
            int j = tid + q * 256;
            int mm = j & 127, k2 = j >> 7;
            cvt_pair(r[q * 2], r[q * 2 + 1], H[k2][mm], L[k2][mm]);
        }
    }
}

__global__ __launch_bounds__(256) void tgemm_kernel(GemmP p) {
    __shared__ unsigned Ah[16][136], Al[16][136];
    __shared__ unsigned Bh[16][136], Bl[16][136];
    int bz = blockIdx.z;
    long long Abase = (long long)bz * p.a_b;
    long long Bbase = (long long)bz * p.b_b;
    int m0 = blockIdx.y * 128, n0 = blockIdx.x * 128;
    int tid = threadIdx.x;
    int warp = tid >> 5, lane = tid & 31;
    int wm = warp >> 2, wn = warp & 3;   // warp tile: 64(m) x 32(n)
    int tig = lane & 3, grp = lane >> 2;

    float acc[4][4][4];
#pragma unroll
    for (int i = 0; i < 4; i++)
#pragma unroll
        for (int j = 0; j < 4; j++)
#pragma unroll
            for (int r = 0; r < 4; r++) acc[i][j][r] = 0.f;

    float regA[16], regB[16];
    int T = p.K / 32;
    load_tile(p.A, Abase, p.a_sm, p.a_sk, m0, 0, tid, regA);
    load_tile(p.Bm, Bbase, p.b_sn, p.b_sk, n0, 0, tid, regB);

    for (int t = 0; t < T; t++) {
        sts_tile(Ah, Al, p.a_sk, tid, regA);
        sts_tile(Bh, Bl, p.b_sk, tid, regB);
        __syncthreads();
        if (t + 1 < T) {  // prefetch next tile: LDG latency hides behind MMAs below
            load_tile(p.A, Abase, p.a_sm, p.a_sk, m0, (t + 1) * 32, tid, regA);
            load_tile(p.Bm, Bbase, p.b_sn, p.b_sk, n0, (t + 1) * 32, tid, regB);
        }
#pragma unroll
        for (int kc2 = 0; kc2 < 16; kc2 += 8) {
            unsigned ah[4][4], al[4][4], bh[4][2], bl[4][2];
#pragma unroll
            for (int mf = 0; mf < 4; mf++) {
                int mr = wm * 64 + mf * 16 + grp;
                ah[mf][0] = Ah[kc2 + tig][mr];
                ah[mf][1] = Ah[kc2 + tig][mr + 8];
                ah[mf][2] = Ah[kc2 + tig + 4][mr];
                ah[mf][3] = Ah[kc2 + tig + 4][mr + 8];
                al[mf][0] = Al[kc2 + tig][mr];
                al[mf][1] = Al[kc2 + tig][mr + 8];
                al[mf][2] = Al[kc2 + tig + 4][mr];
                al[mf][3] = Al[kc2 + tig + 4][mr + 8];
            }
#pragma unroll
            for (int nf = 0; nf < 4; nf++) {
                int nc = wn * 32 + nf * 8 + grp;
                bh[nf][0] = Bh[kc2 + tig][nc];
                bh[nf][1] = Bh[kc2 + tig + 4][nc];
                bl[nf][0] = Bl[kc2 + tig][nc];
                bl[nf][1] = Bl[kc2 + tig + 4][nc];
            }
#pragma unroll
            for (int mf = 0; mf < 4; mf++)
#pragma unroll
                for (int nf = 0; nf < 4; nf++) {
                    mma16(acc[mf][nf], ah[mf], bh[nf]);
                    mma16(acc[mf][nf], ah[mf], bl[nf]);
                    mma16(acc[mf][nf], al[mf], bh[nf]);
                }
        }
        __syncthreads();
    }

    // ---- epilogue ----
#pragma unroll
    for (int mf = 0; mf < 4; mf++) {
#pragma unroll
        for (int nf = 0; nf < 4; nf++) {
#pragma unroll
            for (int half = 0; half < 2; half++) {
                int m = m0 + wm * 64 + mf * 16 + grp + half * 8;
                int n = n0 + wn * 32 + nf * 8 + tig * 2;
                float v0 = acc[mf][nf][half * 2 + 0];
                float v1 = acc[mf][nf][half * 2 + 1];
                if (p.bias) {
                    if (p.bias_per_m) { float bm = p.bias[m]; v0 += bm; v1 += bm; }
                    else { v0 += p.bias[n]; v1 += p.bias[n + 1]; }
                }
                long long cidx = (long long)bz * p.c_b + (long long)m * p.c_row + n;
                if (p.mode == 0) {
                    *(float2*)&p.C[cidx] = make_float2(v0, v1);
                } else if (p.mode == 1) {
                    int tok = p.tokens[bz * SSQ + m];
                    if (tok == 0) { v0 = 0.f; v1 = 0.f; }
                    *(float2*)&p.C[cidx] = make_float2(v0, v1);
                    float2 e = *(const float2*)&p.emb[(long long)bz * p.emb_b + (long long)m * p.N + n];
                    *(float2*)&p.C2[cidx] = make_float2((v0 + e.x) * R2F, (v1 + e.y) * R2F);
                } else {
                    float2 e = *(const float2*)&p.emb[(long long)bz * p.emb_b + (long long)m * p.N + n];
                    *(float2*)&p.C[cidx] = make_float2((v0 + e.x) * R2F, (v1 + e.y) * R2F);
                }
            }
        }
    }
}

// ---------------- vocab GEMM: 1x tf32, pipelined (terminal op, error doesn't compound) ----
// C[m][n] = sum_k A[m][k] * W[k][n] + bias[n];  A:[2048,512] row-major, W:[512,32000] row-major
__global__ __launch_bounds__(256) void vgemm_kernel(const float* __restrict__ A,
                                                    const float* __restrict__ W,
                                                    const float* __restrict__ bias,
                                                    float* __restrict__ C) {
    __shared__ unsigned At[32][136], Bt[32][136];
    int m0 = blockIdx.y * 128, n0 = blockIdx.x * 128;
    int tid = threadIdx.x;
    int warp = tid >> 5, lane = tid & 31;
    int wm = warp >> 2, wn = warp & 3;
    int tig = lane & 3, grp = lane >> 2;

    float acc[4][4][4];
#pragma unroll
    for (int i = 0; i < 4; i++)
#pragma unroll
        for (int j = 0; j < 4; j++)
#pragma unroll
            for (int r = 0; r < 4; r++) acc[i][j][r] = 0.f;

    int am = tid >> 1, akb = (tid & 1) << 4;   // A: 2 threads/row, 16 k each
    float regA[16], regB[16];

    const float* Ap0 = A + (long long)(m0 + am) * DDQ + akb;
#pragma unroll
    for (int u = 0; u < 4; u++) {
        float4 v = *(const float4*)(Ap0 + u * 4);
        regA[u * 4 + 0] = v.x; regA[u * 4 + 1] = v.y; regA[u * 4 + 2] = v.z; regA[u * 4 + 3] = v.w;
    }
#pragma unroll
    for (int q = 0; q < 16; q++) {
        int j = tid + q * 256;
        int nn = j & 127, kk = j >> 7;
        regB[q] = W[(long long)kk * VVQ + n0 + nn];
    }

    int T = DDQ / 32;  // 16
    for (int t = 0; t < T; t++) {
        // STS (convert to tf32)
        {
#pragma unroll
            for (int u = 0; u < 16; u++) At[akb + u][am] = f2tf(regA[u]);
#pragma unroll
            for (int q = 0; q < 16; q++) {
                int j = tid + q * 256;
                int nn = j & 127, kk = j >> 7;
                Bt[kk][nn] = f2tf(regB[q]);
            }
        }
        __syncthreads();
        if (t + 1 < T) {
            int k0 = (t + 1) * 32;
            const float* Ap = A + (long long)(m0 + am) * DDQ + k0 + akb;
#pragma unroll
            for (int u = 0; u < 4; u++) {
                float4 v = *(const float4*)(Ap + u * 4);
                regA[u * 4 + 0] = v.x; regA[u * 4 + 1] = v.y; regA[u * 4 + 2] = v.z; regA[u * 4 + 3] = v.w;
            }
#pragma unroll
            for (int q = 0; q < 16; q++) {
                int j = tid + q * 256;
                int nn = j & 127, kk = j >> 7;
                regB[q] = W[(long long)(k0 + kk) * VVQ + n0 + nn];
            }
        }
#pragma unroll
        for (int ks = 0; ks < 32; ks += 8) {
            unsigned af[4][4], bf[4][2];
#pragma unroll
            for (int mf = 0; mf < 4; mf++) {
                int mr = wm * 64 + mf * 16 + grp;
                af[mf][0] = At[ks + tig][mr];
                af[mf][1] = At[ks + tig][mr + 8];
                af[mf][2] = At[ks + tig + 4][mr];
                af[mf][3] = At[ks + tig + 4][mr + 8];
            }
#pragma unroll
            for (int nf = 0; nf < 4; nf++) {
                int nc = wn * 32 + nf * 8 + grp;
                bf[nf][0] = Bt[ks + tig][nc];
                bf[nf][1] = Bt[ks + tig + 4][nc];
            }
#pragma unroll
            for (int mf = 0; mf < 4; mf++)
#pragma unroll
                for (int nf = 0; nf < 4; nf++) mma8(acc[mf][nf], af[mf], bf[nf]);
        }
        __syncthreads();
    }

#pragma unroll
    for (int mf = 0; mf < 4; mf++)
#pragma unroll
        for (int nf = 0; nf < 4; nf++)
#pragma unroll
            for (int half = 0; half < 2; half++) {
                int m = m0 + wm * 64 + mf * 16 + grp + half * 8;
                int n = n0 + wn * 32 + nf * 8 + tig * 2;
                float v0 = acc[mf][nf][half * 2 + 0] + bias[n];
                float v1 = acc[mf][nf][half * 2 + 1] + bias[n + 1];
                *(float2*)&C[(long long)m * VVQ + n] = make_float2(v0, v1);
            }
}

// ---------------- embeddings ----------------
__global__ void embed_kernel(const int* __restrict__ tokens, const float* __restrict__ tok_emb,
                             const float* __restrict__ pos_emb, float* __restrict__ out, int Slen) {
    int b = blockIdx.y;
    __shared__ int pos[SSQ];
    if (threadIdx.x == 0) {
        int c = 0;
        for (int s = 0; s < Slen; s++) {
            int m = (tokens[b * Slen + s] != 0) ? 1 : 0;
            c += m;
            pos[s] = c * m;
        }
    }
    __syncthreads();
    int chunk = Slen / gridDim.x;
    int s0 = blockIdx.x * chunk;
    for (int idx = threadIdx.x; idx < chunk * DDQ; idx += blockDim.x) {
        int s = s0 + idx / DDQ;
        int d = idx % DDQ;
        int tk = tokens[b * Slen + s];
        out[((long long)b * Slen + s) * DDQ + d] =
            tok_emb[(long long)tk * DDQ + d] + pos_emb[(long long)pos[s] * DDQ + d];
    }
}

// ---------------- im2col (row order ic*3+k so weights are contiguous) ----------------
__global__ void im2col_enc_kernel(const float* __restrict__ x, const int* __restrict__ tokens,
                                  float* __restrict__ out, int total) {
    int idx = blockIdx.x * blockDim.x + threadIdx.x;
    if (idx >= total) return;
    int s = idx % SSQ;
    int r = (idx / SSQ) % (3 * DDQ);
    int b = idx / (SSQ * 3 * DDQ);
    int ic = r / 3, k = r % 3;
    int s2 = s + k - 1;
    float v = 0.f;
    if (s2 >= 0 && s2 < SSQ && tokens[b * SSQ + s2] != 0)
        v = x[((long long)b * DDQ + ic) * SSQ + s2];
    out[idx] = v;
}

__global__ void im2col_dec_kernel(const float* __restrict__ x, float* __restrict__ out, int total) {
    int idx = blockIdx.x * blockDim.x + threadIdx.x;
    if (idx >= total) return;
    int t = idx % TTQ;
    int r = (idx / TTQ) % (3 * DDQ);
    int b = idx / (TTQ * 3 * DDQ);
    int ic = r / 3, k = r % 3;
    int t2 = t + k - 2;  // causal: pad K-1=2 left
    out[idx] = (t2 >= 0) ? x[((long long)b * DDQ + ic) * TTQ + t2] : 0.f;
}

// ---------------- GLU (+ optional residual, in place on x) ----------------
__global__ void glu_res_kernel(const float* __restrict__ y, float* __restrict__ x,
                               int total, int DS, int apply_res) {
    int idx = blockIdx.x * blockDim.x + threadIdx.x;
    if (idx >= total) return;
    int b = idx / DS;
    int rem = idx - b * DS;
    float a = y[(long long)b * 2 * DS + rem];
    float g = y[(long long)b * 2 * DS + DS + rem];
    float v = a / (1.f + expf(-g));
    x[idx] = apply_res ? (v + x[idx]) * R2F : v;
}

// ---------------- decoder combine: x = ((c + att2^T)*R2 + x)*R2 ----------------
__global__ void dec_combine_kernel(float* __restrict__ x, const float* __restrict__ c,
                                   const float* __restrict__ att2, int total) {
    int idx = blockIdx.x * blockDim.x + threadIdx.x;
    if (idx >= total) return;
    int b = idx / (DDQ * TTQ);
    int rem = idx - b * (DDQ * TTQ);
    int ch = rem / TTQ;
    int t = rem % TTQ;
    float cc = (c[idx] + att2[((long long)b * TTQ + t) * DDQ + ch]) * R2F;
    x[idx] = (cc + x[idx]) * R2F;
}

// ---------------- masked softmax over S ----------------
__global__ void softmax_mask_kernel(float* __restrict__ energy, const int* __restrict__ src) {
    int row = blockIdx.x;           // b*T + t
    int b = row / TTQ;
    float* e = energy + (long long)row * SSQ;
    int s = threadIdx.x;            // 256 = S
    float v = (src[b * SSQ + s] == 0) ? -INFINITY : e[s];
    __shared__ float red[SSQ];
    red[s] = v;
    __syncthreads();
    for (int off = 128; off > 0; off >>= 1) {
        if (s < off) red[s] = fmaxf(red[s], red[s + off]);
        __syncthreads();
    }
    float mx = red[0];
    __syncthreads();
    float ex = expf(v - mx);
    red[s] = ex;
    __syncthreads();
    for (int off = 128; off > 0; off >>= 1) {
        if (s < off) red[s] += red[s + off];
        __syncthreads();
    }
    e[s] = ex / red[0];
}

// ---------------- host side ----------------
static void gemm(const float* A, long long a_sm, long long a_sk, long long a_b,
                 const float* Bm, long long b_sk, long long b_sn, long long b_b,
                 float* C, long long c_row, long long c_b,
                 const float* bias, int bias_per_m,
                 int M, int N, int K, int nb,
                 int mode = 0, const int* tokens = nullptr,
                 const float* emb = nullptr, long long emb_b = 0, float* C2 = nullptr) {
    GemmP p;
    p.A = A; p.a_sm = a_sm; p.a_sk = a_sk; p.a_b = a_b;
    p.Bm = Bm; p.b_sk = b_sk; p.b_sn = b_sn; p.b_b = b_b;
    p.C = C; p.c_row = c_row; p.c_b = c_b;
    p.bias = bias; p.bias_per_m = bias_per_m;
    p.M = M; p.N = N; p.K = K; p.mode = mode;
    p.tokens = tokens; p.emb = emb; p.emb_b = emb_b; p.C2 = C2;
    dim3 grid(N / 128, M / 128, nb);
    tgemm_kernel<<<grid, 256>>>(p);
}

extern "C" void kernel_launch(void* const* d_in, const int* in_sizes, int n_in,
                              void* d_out, int out_size) {
    const int*   src        = (const int*)d_in[0];
    const int*   trg        = (const int*)d_in[1];
    const float* enc_tok    = (const float*)d_in[2];
    const float* enc_pos    = (const float*)d_in[3];
    const float* dec_tok    = (const float*)d_in[4];
    const float* dec_pos    = (const float*)d_in[5];
    const float* enc_in_w   = (const float*)d_in[6];
    const float* enc_in_b   = (const float*)d_in[7];
    const float* enc_conv_w = (const float*)d_in[8];
    const float* enc_conv_b = (const float*)d_in[9];
    const float* enc_out_w  = (const float*)d_in[10];
    const float* enc_out_b  = (const float*)d_in[11];
    const float* dec_in_w   = (const float*)d_in[12];
    const float* dec_in_b   = (const float*)d_in[13];
    const float* dec_conv_w = (const float*)d_in[14];
    const float* dec_conv_b = (const float*)d_in[15];
    const float* attn_in_w  = (const float*)d_in[16];
    const float* attn_in_b  = (const float*)d_in[17];
    const float* attn_out_w = (const float*)d_in[18];
    const float* attn_out_b = (const float*)d_in[19];
    const float* dec_out_w  = (const float*)d_in[20];
    const float* dec_out_b  = (const float*)d_in[21];
    const float* vocab_w    = (const float*)d_in[22];
    const float* vocab_b    = (const float*)d_in[23];
    float* logits = (float*)d_out;

    void* sp;
    cudaGetSymbolAddress(&sp, g_scratch);
    float* base = (float*)sp;
    float* enc_emb    = base;
    float* enc_x      = base + 2097152;
    float* im2col     = base + 4194304;
    float* ybuf       = base + 10485760;
    float* enc_conved = base + 14680064;
    float* enc_comb   = base + 16777216;
    float* dec_emb    = base + 18874368;
    float* dec_x      = base + 19922944;
    float* dec_c      = base + 20971520;
    float* qbuf       = base + 22020096;
    float* energy     = base + 23068672;
    float* att        = base + 23592960;
    float* att2       = base + 24641536;

    // ---- embeddings ----
    embed_kernel<<<dim3(4, BB), 256>>>(src, enc_tok, enc_pos, enc_emb, SSQ);
    embed_kernel<<<dim3(4, BB), 256>>>(trg, dec_tok, dec_pos, dec_emb, TTQ);

    // ---- encoder in-projection -> x[b][c][s] ----
    gemm(enc_in_w, 1, DDQ, 0,
         enc_emb, 1, DDQ, (long long)SSQ * DDQ,
         enc_x, SSQ, (long long)DDQ * SSQ,
         enc_in_b, 1, DDQ, SSQ, DDQ, BB);

    // ---- encoder conv stack ----
    for (int l = 0; l < LLQ; l++) {
        int tot = BB * DDQ * 3 * SSQ;
        im2col_enc_kernel<<<(tot + 255) / 256, 256>>>(enc_x, src, im2col, tot);
        gemm(enc_conv_w + (long long)l * 2 * DDQ * DDQ * 3, 3 * DDQ, 1, 0,
             im2col, SSQ, 1, (long long)3 * DDQ * SSQ,
             ybuf, SSQ, (long long)2 * DDQ * SSQ,
             enc_conv_b + l * 2 * DDQ, 1, 2 * DDQ, SSQ, 3 * DDQ, BB);
        int tot2 = BB * DDQ * SSQ;
        glu_res_kernel<<<(tot2 + 255) / 256, 256>>>(ybuf, enc_x, tot2, DDQ * SSQ, 1);
    }

    // ---- encoder out-projection (+pad mask, combined) ----
    gemm(enc_x, 1, SSQ, (long long)DDQ * SSQ,
         enc_out_w, DDQ, 1, 0,
         enc_conved, DDQ, (long long)SSQ * DDQ,
         enc_out_b, 0, SSQ, DDQ, DDQ, BB,
         1, src, enc_emb, (long long)SSQ * DDQ, enc_comb);

    // ---- decoder in-projection -> x[b][c][t] ----
    gemm(dec_in_w, 1, DDQ, 0,
         dec_emb, 1, DDQ, (long long)TTQ * DDQ,
         dec_x, TTQ, (long long)DDQ * TTQ,
         dec_in_b, 1, DDQ, TTQ, DDQ, BB);

    // ---- decoder layers ----
    for (int l = 0; l < LLQ; l++) {
        int tot = BB * DDQ * 3 * TTQ;
        im2col_dec_kernel<<<(tot + 255) / 256, 256>>>(dec_x, im2col, tot);
        gemm(dec_conv_w + (long long)l * 2 * DDQ * DDQ * 3, 3 * DDQ, 1, 0,
             im2col, TTQ, 1, (long long)3 * DDQ * TTQ,
             ybuf, TTQ, (long long)2 * DDQ * TTQ,
             dec_conv_b + l * 2 * DDQ, 1, 2 * DDQ, TTQ, 3 * DDQ, BB);
        int tot2 = BB * DDQ * TTQ;
        glu_res_kernel<<<(tot2 + 255) / 256, 256>>>(ybuf, dec_c, tot2, DDQ * TTQ, 0);

        // q = (c^T @ Wq + bq + emb) * R2
        gemm(dec_c, 1, TTQ, (long long)DDQ * TTQ,
             attn_in_w + (long long)l * DDQ * DDQ, DDQ, 1, 0,
             qbuf, DDQ, (long long)TTQ * DDQ,
             attn_in_b + l * DDQ, 0, TTQ, DDQ, DDQ, BB,
             2, nullptr, dec_emb, (long long)TTQ * DDQ, nullptr);

        // energy = q @ enc_conved^T
        gemm(qbuf, DDQ, 1, (long long)TTQ * DDQ,
             enc_conved, 1, DDQ, (long long)SSQ * DDQ,
             energy, SSQ, (long long)TTQ * SSQ,
             nullptr, 0, TTQ, SSQ, DDQ, BB);

        softmax_mask_kernel<<<BB * TTQ, SSQ>>>(energy, src);

        // att = attn @ enc_combined
        gemm(energy, SSQ, 1, (long long)TTQ * SSQ,
             enc_comb, DDQ, 1, (long long)SSQ * DDQ,
             att, DDQ, (long long)TTQ * DDQ,
             nullptr, 0, TTQ, DDQ, SSQ, BB);

        // att2 = att @ Wout + bout
        gemm(att, DDQ, 1, 0,
             attn_out_w + (long long)l * DDQ * DDQ, DDQ, 1, 0,
             att2, DDQ, 0,
             attn_out_b + l * DDQ, 0, BB * TTQ, DDQ, DDQ, 1);

        int tot3 = BB * DDQ * TTQ;
        dec_combine_kernel<<<(tot3 + 255) / 256, 256>>>(dec_x, dec_c, att2, tot3);
    }

    // ---- decoder out-projection -> [B,T,D] (reuse qbuf) ----
    gemm(dec_x, 1, TTQ, (long long)DDQ * TTQ,
         dec_out_w, DDQ, 1, 0,
         qbuf, DDQ, (long long)TTQ * DDQ,
         dec_out_b, 0, TTQ, DDQ, DDQ, BB);

    // ---- vocab projection -> logits [B*T, V] (dedicated pipelined 1x tf32 kernel) ----
    vgemm_kernel<<<dim3(VVQ / 128, (BB * TTQ) / 128), 256>>>(qbuf, vocab_w, vocab_b, logits);
}